// round 3
// baseline (speedup 1.0000x reference)
#include <cuda_runtime.h>
#include <cstdint>
#include <cstddef>

// ---------------------------------------------------------------------------
// HyperConv: y[b,o,t] = bias[chunk,o] + sum_{tap,cin} x[b,cin,t-tap] * W[chunk, (tap*128+cin)*128+o]
// chunk = b*400 + (t/120); W = w2 @ relu(w1 @ z + b1) + b2 (per chunk)
// ---------------------------------------------------------------------------

#define NB   4
#define ZD   64
#define NK   400
#define TT   48000
#define CI   128
#define CO   128
#define KSZ  3
#define HH   32
#define TKC  120                    // samples per chunk
#define NCH  (NB*NK)                // 1600 chunks
#define RD   (CI*KSZ*CO)            // 49152 rows of w2

// scratch: per-chunk generated weights, chunk-major [chunk][cidx*128+o]
__device__ float g_W[(size_t)NCH * RD];      // 314.6 MB
__device__ float g_hv[NCH * HH];
__device__ float g_bias[NCH * CO];

// ---------------------------------------------------------------------------
// Kernel 1: per-chunk MLP hiddens + bias vector
// ---------------------------------------------------------------------------
__global__ __launch_bounds__(128) void prep_kernel(
    const float* __restrict__ z,
    const float* __restrict__ w1, const float* __restrict__ b1,
    const float* __restrict__ bw1, const float* __restrict__ bb1,
    const float* __restrict__ bw2, const float* __restrict__ bb2)
{
    int chunk = blockIdx.x;
    int b = chunk / NK, kk = chunk % NK;
    __shared__ float zv[ZD];
    __shared__ float hb[HH];
    int tid = threadIdx.x;
    if (tid < ZD) zv[tid] = z[((size_t)b * ZD + tid) * NK + kk];
    __syncthreads();
    if (tid < HH) {
        float s = b1[tid];
        #pragma unroll 8
        for (int j = 0; j < ZD; j++) s += w1[tid * ZD + j] * zv[j];
        g_hv[chunk * HH + tid] = fmaxf(s, 0.f);
    } else if (tid < 2 * HH) {
        int o = tid - HH;
        float s = bb1[o];
        #pragma unroll 8
        for (int j = 0; j < ZD; j++) s += bw1[o * ZD + j] * zv[j];
        hb[o] = fmaxf(s, 0.f);
    }
    __syncthreads();
    {
        float s = bb2[tid];
        #pragma unroll
        for (int h = 0; h < HH; h++) s += bw2[tid * HH + h] * hb[h];
        g_bias[chunk * CO + tid] = s;
    }
}

// ---------------------------------------------------------------------------
// Kernel 2: weight generation GEMM  g_W[c][r] = sum_h w2[r][h]*hv[c][h] + b2[r]
// M=49152 (r), N=1600 (chunk), K=32.  Block tile 128r x 128c, thread 16r x 4c.
// ---------------------------------------------------------------------------
__global__ __launch_bounds__(256) void wgen_kernel(
    const float* __restrict__ w2, const float* __restrict__ b2)
{
    __shared__ __align__(16) float as[HH * 132];   // [k][r], padded
    __shared__ __align__(16) float bs[HH * 132];   // [k][c], padded
    int tid = threadIdx.x;
    int r0 = blockIdx.x * 128;
    int c0 = blockIdx.y * 128;

    // load w2 tile (transposed into k-major)
    for (int i4 = tid; i4 < 1024; i4 += 256) {
        int r = i4 >> 3, h4 = i4 & 7;
        float4 v = *(const float4*)(w2 + (size_t)(r0 + r) * HH + h4 * 4);
        as[(h4 * 4 + 0) * 132 + r] = v.x;
        as[(h4 * 4 + 1) * 132 + r] = v.y;
        as[(h4 * 4 + 2) * 132 + r] = v.z;
        as[(h4 * 4 + 3) * 132 + r] = v.w;
    }
    // load hv tile (transposed into k-major), clamp OOB chunks
    for (int i4 = tid; i4 < 1024; i4 += 256) {
        int c = i4 >> 3, h4 = i4 & 7;
        int cc = c0 + c; if (cc >= NCH) cc = NCH - 1;
        float4 v = *(const float4*)(g_hv + (size_t)cc * HH + h4 * 4);
        bs[(h4 * 4 + 0) * 132 + c] = v.x;
        bs[(h4 * 4 + 1) * 132 + c] = v.y;
        bs[(h4 * 4 + 2) * 132 + c] = v.z;
        bs[(h4 * 4 + 3) * 132 + c] = v.w;
    }
    __syncthreads();

    int tx = tid & 31;          // chunk sub-tile: c = c0 + tx*4 + j
    int ty = tid >> 5;          // row sub-tile (== warp id): r = r0 + ty*16 + i
    float acc[4][16];
    #pragma unroll
    for (int j = 0; j < 4; j++)
        #pragma unroll
        for (int i = 0; i < 16; i++) acc[j][i] = 0.f;

    #pragma unroll 8
    for (int k = 0; k < HH; k++) {
        const float* ar = as + k * 132 + ty * 16;   // warp-uniform (broadcast)
        float av[16];
        #pragma unroll
        for (int u = 0; u < 4; u++) {
            float4 v = *(const float4*)(ar + u * 4);
            av[u * 4 + 0] = v.x; av[u * 4 + 1] = v.y;
            av[u * 4 + 2] = v.z; av[u * 4 + 3] = v.w;
        }
        float4 bq = *(const float4*)(bs + k * 132 + tx * 4);
        float bv[4] = {bq.x, bq.y, bq.z, bq.w};
        #pragma unroll
        for (int j = 0; j < 4; j++)
            #pragma unroll
            for (int i = 0; i < 16; i++)
                acc[j][i] += bv[j] * av[i];
    }

    float bias[16];
    #pragma unroll
    for (int u = 0; u < 4; u++) {
        float4 v = *(const float4*)(b2 + r0 + ty * 16 + u * 4);
        bias[u * 4 + 0] = v.x; bias[u * 4 + 1] = v.y;
        bias[u * 4 + 2] = v.z; bias[u * 4 + 3] = v.w;
    }
    #pragma unroll
    for (int j = 0; j < 4; j++) {
        int c = c0 + tx * 4 + j;
        if (c < NCH) {
            float* dst = g_W + (size_t)c * RD + r0 + ty * 16;
            #pragma unroll
            for (int u = 0; u < 4; u++) {
                float4 o;
                o.x = acc[j][u * 4 + 0] + bias[u * 4 + 0];
                o.y = acc[j][u * 4 + 1] + bias[u * 4 + 1];
                o.z = acc[j][u * 4 + 2] + bias[u * 4 + 2];
                o.w = acc[j][u * 4 + 3] + bias[u * 4 + 3];
                *(float4*)(dst + u * 4) = o;
            }
        }
    }
}

// ---------------------------------------------------------------------------
// Kernel 3: per-chunk conv GEMM [120 x 384] @ [384 x 128]
// One block per chunk, 256 threads. x tile in smem, W staged by cp.async
// (double-buffered, 32 cin x 3 taps per stage). Thread: 15 contiguous t x 4 o.
// 3 taps share x values (17 loads feed 180 FFMA per cin).
// ---------------------------------------------------------------------------
#define XS_STRIDE 124
#define XS_FLOATS (CI * XS_STRIDE)            // 15872
#define WB_FLOATS (KSZ * 32 * CO)             // 12288 per buffer
#define CONV_SMEM_BYTES ((XS_FLOATS + 2 * WB_FLOATS) * 4)   // 161792 B

__device__ __forceinline__ void cp_async16(float* dst, const float* src) {
    unsigned s = (unsigned)__cvta_generic_to_shared(dst);
    asm volatile("cp.async.cg.shared.global [%0], [%1], 16;" :: "r"(s), "l"(src));
}
__device__ __forceinline__ void cp_commit() {
    asm volatile("cp.async.commit_group;");
}

__global__ __launch_bounds__(256, 1) void conv_kernel(
    const float* __restrict__ x, float* __restrict__ out)
{
    extern __shared__ __align__(16) float sm[];
    float* xs = sm;                      // [CI][XS_STRIDE], j = t - t0 + 2
    float* wb = sm + XS_FLOATS;          // [2][3][32][128]

    int chunk = blockIdx.x;
    int b = chunk / NK, kk = chunk % NK;
    int t0 = kk * TKC;
    int tid = threadIdx.x, lane = tid & 31, warp = tid >> 5;

    const float* Wc = g_W + (size_t)chunk * RD;

    // stage cb=0 weights
    #pragma unroll
    for (int i = 0; i < 12; i++) {
        int i4 = tid + i * 256;              // 0..3071 float4s
        int tap = i4 >> 10, rem = i4 & 1023;
        cp_async16(wb + tap * 4096 + rem * 4,
                   Wc + ((size_t)(tap * CI + 0 * 32) * CO) + rem * 4);
    }
    cp_commit();

    // load x tile: j in [0,122), t = t0 - 2 + j  (zero-pad t<0)
    const float* xb = x + (size_t)b * CI * TT;
    for (int idx = tid; idx < CI * 122; idx += 256) {
        int cin = idx / 122, j = idx - cin * 122;
        int t = t0 - 2 + j;
        xs[cin * XS_STRIDE + j] = (t >= 0) ? xb[(size_t)cin * TT + t] : 0.f;
    }

    // accumulators init with bias (broadcast over t)
    float acc[15][4];
    float4 bv = *(const float4*)(g_bias + (size_t)chunk * CO + lane * 4);
    #pragma unroll
    for (int r = 0; r < 15; r++) {
        acc[r][0] = bv.x; acc[r][1] = bv.y; acc[r][2] = bv.z; acc[r][3] = bv.w;
    }

    int tb = warp * 15;   // this warp's first t (contiguous 15 samples)

    for (int cb = 0; cb < 4; cb++) {
        if (cb < 3) {
            float* nbuf = wb + ((cb + 1) & 1) * WB_FLOATS;
            #pragma unroll
            for (int i = 0; i < 12; i++) {
                int i4 = tid + i * 256;
                int tap = i4 >> 10, rem = i4 & 1023;
                cp_async16(nbuf + tap * 4096 + rem * 4,
                           Wc + ((size_t)(tap * CI + (cb + 1) * 32) * CO) + rem * 4);
            }
            cp_commit();
            asm volatile("cp.async.wait_group 1;");
        } else {
            asm volatile("cp.async.wait_group 0;");
        }
        __syncthreads();   // current buffer (and xs on cb==0) ready

        const float* wbp = wb + (cb & 1) * WB_FLOATS;
        #pragma unroll 2
        for (int cl = 0; cl < 32; cl++) {
            int cin = cb * 32 + cl;
            const float* xp = xs + cin * XS_STRIDE + tb;
            float xv[17];
            #pragma unroll
            for (int m = 0; m < 17; m++) xv[m] = xp[m];   // broadcast LDS

            float4 w0 = *(const float4*)(wbp + (0 * 32 + cl) * CO + lane * 4);
            float4 w1 = *(const float4*)(wbp + (1 * 32 + cl) * CO + lane * 4);
            float4 w2v = *(const float4*)(wbp + (2 * 32 + cl) * CO + lane * 4);

            #pragma unroll
            for (int r = 0; r < 15; r++) {
                // tap 0 uses x[t], tap 1 x[t-1], tap 2 x[t-2]; j = t - t0 + 2
                float x2 = xv[r + 2], x1 = xv[r + 1], x0 = xv[r];
                acc[r][0] += x2 * w0.x; acc[r][0] += x1 * w1.x; acc[r][0] += x0 * w2v.x;
                acc[r][1] += x2 * w0.y; acc[r][1] += x1 * w1.y; acc[r][1] += x0 * w2v.y;
                acc[r][2] += x2 * w0.z; acc[r][2] += x1 * w1.z; acc[r][2] += x0 * w2v.z;
                acc[r][3] += x2 * w0.w; acc[r][3] += x1 * w1.w; acc[r][3] += x0 * w2v.w;
            }
        }
        __syncthreads();   // done reading this buffer before it is overwritten
    }

    // epilogue: out[b, o, t0+tb+r], o = lane*4+q — 15 contiguous floats per (o)
    float* ob = out + (size_t)b * CO * TT + t0 + tb;
    #pragma unroll
    for (int q = 0; q < 4; q++) {
        float* op = ob + (size_t)(lane * 4 + q) * TT;
        #pragma unroll
        for (int r = 0; r < 15; r++) op[r] = acc[r][q];
    }
}

// ---------------------------------------------------------------------------
extern "C" void kernel_launch(void* const* d_in, const int* in_sizes, int n_in,
                              void* d_out, int out_size)
{
    const float* x   = (const float*)d_in[0];
    const float* z   = (const float*)d_in[1];
    const float* w1  = (const float*)d_in[2];
    const float* b1  = (const float*)d_in[3];
    const float* w2  = (const float*)d_in[4];
    const float* b2  = (const float*)d_in[5];
    const float* bw1 = (const float*)d_in[6];
    const float* bb1 = (const float*)d_in[7];
    const float* bw2 = (const float*)d_in[8];
    const float* bb2 = (const float*)d_in[9];
    float* out = (float*)d_out;

    cudaFuncSetAttribute(conv_kernel,
                         cudaFuncAttributeMaxDynamicSharedMemorySize,
                         CONV_SMEM_BYTES);

    prep_kernel<<<NCH, 128>>>(z, w1, b1, bw1, bb1, bw2, bb2);
    wgen_kernel<<<dim3(RD / 128, (NCH + 127) / 128), 256>>>(w2, b2);
    conv_kernel<<<NCH, 256, CONV_SMEM_BYTES>>>(x, out);
}